// round 7
// baseline (speedup 1.0000x reference)
#include <cuda_runtime.h>
#include <cuda_bf16.h>
#include <cstdint>

// ---------------------------------------------------------------------------
// RecurrentGraphNeuralNet v6: update GEMM + prediction head on HMMA
// (mma.sync.m16n8k16 bf16, sm_80+ path -> compiles for base sm_100),
// split-precision hi/lo, 3 accumulating passes => ~fp32 accuracy (~1.5e-5).
//   agg[d] = sum x[src]  (red.global.v4, unchanged, at LTS roofline)
//   x_new  = relu([mean|u] @ [W;B] + b)   main HMMA GEMM, K=128
//   y      = x_new @ Wp + bp              head HMMA, A-frags from acc regs
// ---------------------------------------------------------------------------

#define MAXN 100000

__device__ float g_agg[(long long)MAXN * 64];
__device__ float g_deg[MAXN];
__device__ int   g_is64;

// ---------------------------------------------------------------------------
__device__ __forceinline__ uint32_t smem_u32(const void* p) {
    uint32_t a;
    asm("{ .reg .u64 t; cvta.to.shared.u64 t, %1; cvt.u32.u64 %0, t; }"
        : "=r"(a) : "l"(p));
    return a;
}
__device__ __forceinline__ void ldsm_x4(uint32_t addr, uint32_t r[4]) {
    asm volatile("ldmatrix.sync.aligned.m8n8.x4.shared.b16 {%0,%1,%2,%3}, [%4];"
        : "=r"(r[0]), "=r"(r[1]), "=r"(r[2]), "=r"(r[3]) : "r"(addr));
}
__device__ __forceinline__ void ldsm_x2(uint32_t addr, uint32_t r[2]) {
    asm volatile("ldmatrix.sync.aligned.m8n8.x2.shared.b16 {%0,%1}, [%2];"
        : "=r"(r[0]), "=r"(r[1]) : "r"(addr));
}
__device__ __forceinline__ void mma16816(float d[4], const uint32_t a[4],
                                         const uint32_t b[2]) {
    asm volatile(
        "mma.sync.aligned.m16n8k16.row.col.f32.bf16.bf16.f32 "
        "{%0,%1,%2,%3}, {%4,%5,%6,%7}, {%8,%9}, {%0,%1,%2,%3};"
        : "+f"(d[0]), "+f"(d[1]), "+f"(d[2]), "+f"(d[3])
        : "r"(a[0]), "r"(a[1]), "r"(a[2]), "r"(a[3]), "r"(b[0]), "r"(b[1]));
}
__device__ __forceinline__ uint32_t pack_bf2(float lo, float hi) {
    __nv_bfloat162 h = __floats2bfloat162_rn(lo, hi);   // .x = lo half (low 16b)
    return *reinterpret_cast<uint32_t*>(&h);
}
__device__ __forceinline__ float bf_lo(uint32_t w) {
    __nv_bfloat16 h = *reinterpret_cast<__nv_bfloat16*>(&w);
    return __bfloat162float(h);
}
__device__ __forceinline__ float bf_hi(uint32_t w) {
    uint32_t s = w >> 16;
    __nv_bfloat16 h = *reinterpret_cast<__nv_bfloat16*>(&s);
    return __bfloat162float(h);
}

// SMEM layout (bytes). Padded strides: A 136 bf16 (272B), W 136, Wp 72 —
// odd multiples of 16B => conflict-free ldmatrix.
#define SO_AHI   0            // 128 x 136 bf16 = 34816
#define SO_ALO   34816        // 34816
#define SO_WHI   69632        // 64 x 136 bf16 = 17408
#define SO_WLO   87040        // 17408
#define SO_WPH   104448       // 32 x 72 bf16 = 4608
#define SO_WPL   109056       // 4608
#define SO_INVD  113664       // 128 f32
#define SO_BS    114176       // 64 f32
#define SO_BPS   114432       // 32 f32
#define SMEM_BYTES 114560     // x2 blocks = 229120 <= 233472 (228KB/SM)

// ---------------------------------------------------------------------------
__global__ void detect_idx_kernel(const void* ei, int E, int N) {
    if (blockIdx.x == 0 && threadIdx.x == 0) {
        const long long* p = (const long long*)ei;
        int is64 = 1;
        #pragma unroll
        for (int i = 0; i < 8; i++) {
            long long v = p[i];
            if (v < 0 || v >= (long long)N) { is64 = 0; break; }
        }
        g_is64 = is64;
    }
}

__global__ void init_kernel(long long nagg4, int n) {
    long long i = (long long)blockIdx.x * blockDim.x + threadIdx.x;
    if (i < nagg4)
        *reinterpret_cast<float4*>(g_agg + i * 4) = make_float4(0.f, 0.f, 0.f, 0.f);
    if (i < n) g_deg[i] = 0.f;
}

__global__ __launch_bounds__(256) void scatter_kernel(
    const float* __restrict__ x, const void* __restrict__ ei_raw, int E)
{
    long long idx = (long long)blockIdx.x * blockDim.x + threadIdx.x;
    long long total = (long long)E * 16;
    if (idx >= total) return;

    const int is64 = g_is64;
    int e  = (int)(idx >> 4);
    int f4 = ((int)idx & 15) * 4;

    int s, d;
    if (is64) {
        const long long* ei = (const long long*)ei_raw;
        s = (int)ei[e];
        d = (int)ei[(long long)E + e];
    } else {
        const int* ei = (const int*)ei_raw;
        s = ei[e];
        d = ei[E + e];
    }

    float4 v = *reinterpret_cast<const float4*>(x + (long long)s * 64 + f4);
    float* dst = g_agg + (long long)d * 64 + f4;
    asm volatile("red.global.add.v4.f32 [%0], {%1, %2, %3, %4};"
                 :: "l"(dst), "f"(v.x), "f"(v.y), "f"(v.z), "f"(v.w)
                 : "memory");

    if ((idx & 15) == 0) atomicAdd(&g_deg[d], 1.0f);
}

// ---------------------------------------------------------------------------
// 128 nodes/block, 128 threads (4 warps); warp w owns rows [w*32, w*32+32).
__global__ __launch_bounds__(128) void update_kernel(
    const float* __restrict__ u, const float* __restrict__ W,
    const float* __restrict__ Bm, const float* __restrict__ b,
    const float* __restrict__ Wp, const float* __restrict__ bp,
    float* __restrict__ out, int N)
{
    extern __shared__ char smem[];
    const uint32_t sb = smem_u32(smem);
    const int t = threadIdx.x;
    const int l = t & 31;
    const int w = t >> 5;
    const int base = blockIdx.x * 128;

    float* invd_sm = (float*)(smem + SO_INVD);
    float* bs      = (float*)(smem + SO_BS);
    float* bps     = (float*)(smem + SO_BPS);

    // --- prologue: invd, biases ---
    {
        int gn = base + t;
        invd_sm[t] = (gn < N) ? 1.0f / fmaxf(g_deg[gn], 1.0f) : 0.f;
    }
    if (t < 64) bs[t] = b[t];
    if (t >= 64 && t < 96) bps[t - 64] = bp[t - 64];
    __syncthreads();

    // --- stage A = [mean | u], split hi/lo, padded stride 136 ---
    for (int i = t; i < 4096; i += 128) {
        int node = i >> 5, ch = i & 31;          // ch: 16 mean chunks + 16 u
        int gn = base + node;
        float4 v = make_float4(0.f, 0.f, 0.f, 0.f);
        if (gn < N) {
            if (ch < 16) {
                v = *reinterpret_cast<const float4*>(g_agg + (long long)gn * 64 + ch * 4);
                float s = invd_sm[node];
                v.x *= s; v.y *= s; v.z *= s; v.w *= s;
            } else {
                v = *reinterpret_cast<const float4*>(u + (long long)gn * 64 + (ch - 16) * 4);
            }
        }
        uint32_t h01 = pack_bf2(v.x, v.y);
        uint32_t h23 = pack_bf2(v.z, v.w);
        uint32_t l01 = pack_bf2(v.x - bf_lo(h01), v.y - bf_hi(h01));
        uint32_t l23 = pack_bf2(v.z - bf_lo(h23), v.w - bf_hi(h23));
        uint32_t off = (uint32_t)(node * 136 + ch * 4) * 2;
        *reinterpret_cast<uint2*>(smem + SO_AHI + off) = make_uint2(h01, h23);
        *reinterpret_cast<uint2*>(smem + SO_ALO + off) = make_uint2(l01, l23);
    }

    // --- stage Wt[n][k] = (k<64 ? W[k][n] : Bm[k-64][n]), hi/lo ---
    for (int i = t; i < 8192; i += 128) {
        int n = i & 63, k = i >> 6;
        float wv = (k < 64) ? W[k * 64 + n] : Bm[(k - 64) * 64 + n];
        __nv_bfloat16 whi = __float2bfloat16(wv);
        __nv_bfloat16 wlo = __float2bfloat16(wv - __bfloat162float(whi));
        uint32_t off = (uint32_t)(n * 136 + k) * 2;
        *reinterpret_cast<__nv_bfloat16*>(smem + SO_WHI + off) = whi;
        *reinterpret_cast<__nv_bfloat16*>(smem + SO_WLO + off) = wlo;
    }

    // --- stage WpT[p][k] = Wp[k][p], hi/lo, stride 72 ---
    for (int i = t; i < 2048; i += 128) {
        int p = i & 31, k = i >> 5;
        float wv = Wp[k * 32 + p];
        __nv_bfloat16 whi = __float2bfloat16(wv);
        __nv_bfloat16 wlo = __float2bfloat16(wv - __bfloat162float(whi));
        uint32_t off = (uint32_t)(p * 72 + k) * 2;
        *reinterpret_cast<__nv_bfloat16*>(smem + SO_WPH + off) = whi;
        *reinterpret_cast<__nv_bfloat16*>(smem + SO_WPL + off) = wlo;
    }
    __syncthreads();

    // --- main GEMM: acc[m][n] += A @ Wt, 3 passes (hh, hl, lh) ---
    float acc[2][8][4];
    #pragma unroll
    for (int m = 0; m < 2; m++)
        #pragma unroll
        for (int n = 0; n < 8; n++)
            #pragma unroll
            for (int q = 0; q < 4; q++) acc[m][n][q] = 0.f;

    const uint32_t a_off = (uint32_t)((w * 32 + (l & 15)) * 136 + (l >> 4) * 8) * 2;
    const uint32_t b_off = (uint32_t)((l & 7) * 136 + ((l >> 3) & 1) * 8) * 2;

    auto gemm_pass = [&](uint32_t abase, uint32_t bbase) {
        #pragma unroll
        for (int kt = 0; kt < 8; kt++) {
            uint32_t af[2][4];
            #pragma unroll
            for (int m = 0; m < 2; m++)
                ldsm_x4(abase + a_off + m * 4352 + kt * 32, af[m]);
            uint32_t bf[8][2];
            #pragma unroll
            for (int n = 0; n < 8; n++)
                ldsm_x2(bbase + b_off + n * 2176 + kt * 32, bf[n]);
            #pragma unroll
            for (int m = 0; m < 2; m++)
                #pragma unroll
                for (int n = 0; n < 8; n++)
                    mma16816(acc[m][n], af[m], bf[n]);
        }
    };
    gemm_pass(sb + SO_AHI, sb + SO_WHI);
    gemm_pass(sb + SO_AHI, sb + SO_WLO);
    gemm_pass(sb + SO_ALO, sb + SO_WHI);

    // --- epilogue: bias+relu, store x_new, build head A-frags from regs ---
    // acc d-layout: rows {l>>2, l>>2+8} of tile, cols {(l&3)*2, +1} of n-tile
    // == exactly the A-fragment layout for the head GEMM (k = old n dim).
    uint32_t xh[2][8][2], xl[2][8][2];
    #pragma unroll
    for (int m = 0; m < 2; m++) {
        int r0 = base + w * 32 + m * 16 + (l >> 2);
        #pragma unroll
        for (int n = 0; n < 8; n++) {
            int c = n * 8 + (l & 3) * 2;
            float b0 = bs[c], b1 = bs[c + 1];
            float d0 = fmaxf(acc[m][n][0] + b0, 0.f);
            float d1 = fmaxf(acc[m][n][1] + b1, 0.f);
            float d2 = fmaxf(acc[m][n][2] + b0, 0.f);
            float d3 = fmaxf(acc[m][n][3] + b1, 0.f);
            uint32_t h01 = pack_bf2(d0, d1);
            uint32_t h23 = pack_bf2(d2, d3);
            xh[m][n][0] = h01;
            xh[m][n][1] = h23;
            xl[m][n][0] = pack_bf2(d0 - bf_lo(h01), d1 - bf_hi(h01));
            xl[m][n][1] = pack_bf2(d2 - bf_lo(h23), d3 - bf_hi(h23));
            if (r0 < N)
                *reinterpret_cast<float2*>(out + (long long)r0 * 64 + c) =
                    make_float2(d0, d1);
            if (r0 + 8 < N)
                *reinterpret_cast<float2*>(out + (long long)(r0 + 8) * 64 + c) =
                    make_float2(d2, d3);
        }
    }

    // --- head GEMM: y = x_new @ Wp, 3 passes, A-frags straight from regs ---
    float y[2][4][4];
    #pragma unroll
    for (int m = 0; m < 2; m++)
        #pragma unroll
        for (int nt = 0; nt < 4; nt++)
            #pragma unroll
            for (int q = 0; q < 4; q++) y[m][nt][q] = 0.f;

    const uint32_t p_off = (uint32_t)((l & 7) * 72 + ((l >> 3) & 1) * 8) * 2;

    auto head_pass = [&](uint32_t (*xf)[8][2], uint32_t pbase) {
        #pragma unroll
        for (int kk = 0; kk < 4; kk++) {
            uint32_t bf[4][2];
            #pragma unroll
            for (int nt = 0; nt < 4; nt++)
                ldsm_x2(pbase + p_off + nt * 1152 + kk * 32, bf[nt]);
            #pragma unroll
            for (int m = 0; m < 2; m++) {
                uint32_t afr[4] = { xf[m][2 * kk][0], xf[m][2 * kk][1],
                                    xf[m][2 * kk + 1][0], xf[m][2 * kk + 1][1] };
                #pragma unroll
                for (int nt = 0; nt < 4; nt++)
                    mma16816(y[m][nt], afr, bf[nt]);
            }
        }
    };
    head_pass(xh, sb + SO_WPH);
    head_pass(xh, sb + SO_WPL);
    head_pass(xl, sb + SO_WPH);

    // --- store y ---
    float* outy = out + (long long)N * 64;
    #pragma unroll
    for (int m = 0; m < 2; m++) {
        int r0 = base + w * 32 + m * 16 + (l >> 2);
        #pragma unroll
        for (int nt = 0; nt < 4; nt++) {
            int c = nt * 8 + (l & 3) * 2;
            float q0 = y[m][nt][0] + bps[c];
            float q1 = y[m][nt][1] + bps[c + 1];
            float q2 = y[m][nt][2] + bps[c];
            float q3 = y[m][nt][3] + bps[c + 1];
            if (r0 < N)
                *reinterpret_cast<float2*>(outy + (long long)r0 * 32 + c) =
                    make_float2(q0, q1);
            if (r0 + 8 < N)
                *reinterpret_cast<float2*>(outy + (long long)(r0 + 8) * 32 + c) =
                    make_float2(q2, q3);
        }
    }
}

// ---------------------------------------------------------------------------
extern "C" void kernel_launch(void* const* d_in, const int* in_sizes, int n_in,
                              void* d_out, int out_size)
{
    const float* x  = (const float*)d_in[0];
    const float* u  = (const float*)d_in[1];
    const void*  ei = d_in[2];
    const float* W  = (const float*)d_in[3];
    const float* B  = (const float*)d_in[4];
    const float* b  = (const float*)d_in[5];
    const float* Wp = (const float*)d_in[6];
    const float* bp = (const float*)d_in[7];
    float* out = (float*)d_out;

    int N = in_sizes[0] / 64;
    int E = in_sizes[2] / 2;

    cudaFuncSetAttribute(update_kernel,
                         cudaFuncAttributeMaxDynamicSharedMemorySize, SMEM_BYTES);

    detect_idx_kernel<<<1, 32>>>(ei, E, N);

    long long nagg4 = ((long long)N * 64) / 4;
    int init_blocks = (int)((nagg4 + 255) / 256);
    init_kernel<<<init_blocks, 256>>>(nagg4, N);

    long long sc_threads = (long long)E * 16;
    int sc_blocks = (int)((sc_threads + 255) / 256);
    scatter_kernel<<<sc_blocks, 256>>>(x, ei, E);

    int up_blocks = (N + 127) / 128;
    update_kernel<<<up_blocks, 128, SMEM_BYTES>>>(u, W, B, b, Wp, bp, out, N);
}

// round 8
// speedup vs baseline: 1.2694x; 1.2694x over previous
#include <cuda_runtime.h>
#include <cuda_bf16.h>
#include <cstdint>

// ---------------------------------------------------------------------------
// RecurrentGraphNeuralNet v7: HMMA (mma.sync.m16n8k16 bf16) update + head,
// split-precision hi/lo, 3 accumulating passes (~1.5e-5 numerics).
// v7 shape fix: 256 threads / 8 warps per 128-node block, 1 m-tile per warp,
// launch_bounds(256,2) -> 2 blocks/SM, ldsm_x4 for B fragments.
// ---------------------------------------------------------------------------

#define MAXN 100000

__device__ float g_agg[(long long)MAXN * 64];
__device__ float g_deg[MAXN];
__device__ int   g_is64;

// ---------------------------------------------------------------------------
__device__ __forceinline__ uint32_t smem_u32(const void* p) {
    uint32_t a;
    asm("{ .reg .u64 t; cvta.to.shared.u64 t, %1; cvt.u32.u64 %0, t; }"
        : "=r"(a) : "l"(p));
    return a;
}
__device__ __forceinline__ void ldsm_x4(uint32_t addr, uint32_t r[4]) {
    asm volatile("ldmatrix.sync.aligned.m8n8.x4.shared.b16 {%0,%1,%2,%3}, [%4];"
        : "=r"(r[0]), "=r"(r[1]), "=r"(r[2]), "=r"(r[3]) : "r"(addr));
}
__device__ __forceinline__ void mma16816(float d[4], const uint32_t a[4],
                                         const uint32_t b[2]) {
    asm volatile(
        "mma.sync.aligned.m16n8k16.row.col.f32.bf16.bf16.f32 "
        "{%0,%1,%2,%3}, {%4,%5,%6,%7}, {%8,%9}, {%0,%1,%2,%3};"
        : "+f"(d[0]), "+f"(d[1]), "+f"(d[2]), "+f"(d[3])
        : "r"(a[0]), "r"(a[1]), "r"(a[2]), "r"(a[3]), "r"(b[0]), "r"(b[1]));
}
__device__ __forceinline__ uint32_t pack_bf2(float lo, float hi) {
    __nv_bfloat162 h = __floats2bfloat162_rn(lo, hi);
    return *reinterpret_cast<uint32_t*>(&h);
}
__device__ __forceinline__ float bf_lo(uint32_t w) {
    __nv_bfloat16 h = *reinterpret_cast<__nv_bfloat16*>(&w);
    return __bfloat162float(h);
}
__device__ __forceinline__ float bf_hi(uint32_t w) {
    uint32_t s = w >> 16;
    __nv_bfloat16 h = *reinterpret_cast<__nv_bfloat16*>(&s);
    return __bfloat162float(h);
}

// SMEM layout (bytes); strides 136/72 bf16 = odd x 16B -> conflict-free ldsm.
#define SO_AHI   0            // 128 x 136 bf16
#define SO_ALO   34816
#define SO_WHI   69632        // 64 x 136 bf16
#define SO_WLO   87040
#define SO_WPH   104448       // 32 x 72 bf16
#define SO_WPL   109056
#define SO_INVD  113664       // 128 f32
#define SO_BS    114176       // 64 f32
#define SO_BPS   114432       // 32 f32
#define SMEM_BYTES 114560

// ---------------------------------------------------------------------------
__global__ void detect_idx_kernel(const void* ei, int E, int N) {
    if (blockIdx.x == 0 && threadIdx.x == 0) {
        const long long* p = (const long long*)ei;
        int is64 = 1;
        #pragma unroll
        for (int i = 0; i < 8; i++) {
            long long v = p[i];
            if (v < 0 || v >= (long long)N) { is64 = 0; break; }
        }
        g_is64 = is64;
    }
}

__global__ void init_kernel(long long nagg4, int n) {
    long long i = (long long)blockIdx.x * blockDim.x + threadIdx.x;
    if (i < nagg4)
        *reinterpret_cast<float4*>(g_agg + i * 4) = make_float4(0.f, 0.f, 0.f, 0.f);
    if (i < n) g_deg[i] = 0.f;
}

__global__ __launch_bounds__(256) void scatter_kernel(
    const float* __restrict__ x, const void* __restrict__ ei_raw, int E)
{
    long long idx = (long long)blockIdx.x * blockDim.x + threadIdx.x;
    long long total = (long long)E * 16;
    if (idx >= total) return;

    const int is64 = g_is64;
    int e  = (int)(idx >> 4);
    int f4 = ((int)idx & 15) * 4;

    int s, d;
    if (is64) {
        const long long* ei = (const long long*)ei_raw;
        s = (int)ei[e];
        d = (int)ei[(long long)E + e];
    } else {
        const int* ei = (const int*)ei_raw;
        s = ei[e];
        d = ei[E + e];
    }

    float4 v = *reinterpret_cast<const float4*>(x + (long long)s * 64 + f4);
    float* dst = g_agg + (long long)d * 64 + f4;
    asm volatile("red.global.add.v4.f32 [%0], {%1, %2, %3, %4};"
                 :: "l"(dst), "f"(v.x), "f"(v.y), "f"(v.z), "f"(v.w)
                 : "memory");

    if ((idx & 15) == 0) atomicAdd(&g_deg[d], 1.0f);
}

// ---------------------------------------------------------------------------
// 128 nodes/block, 256 threads (8 warps); warp w owns rows [w*16, w*16+16).
__global__ __launch_bounds__(256, 2) void update_kernel(
    const float* __restrict__ u, const float* __restrict__ W,
    const float* __restrict__ Bm, const float* __restrict__ b,
    const float* __restrict__ Wp, const float* __restrict__ bp,
    float* __restrict__ out, int N)
{
    extern __shared__ char smem[];
    const uint32_t sb = smem_u32(smem);
    const int t = threadIdx.x;
    const int l = t & 31;
    const int w = t >> 5;
    const int base = blockIdx.x * 128;

    float* invd_sm = (float*)(smem + SO_INVD);
    float* bs      = (float*)(smem + SO_BS);
    float* bps     = (float*)(smem + SO_BPS);

    // --- prologue ---
    if (t < 128) {
        int gn = base + t;
        invd_sm[t] = (gn < N) ? 1.0f / fmaxf(g_deg[gn], 1.0f) : 0.f;
    }
    if (t >= 128 && t < 192) bs[t - 128] = b[t - 128];
    if (t >= 192 && t < 224) bps[t - 192] = bp[t - 192];
    __syncthreads();

    // --- stage A = [mean | u], hi/lo, stride 136 ---
    #pragma unroll
    for (int it = 0; it < 16; it++) {
        int i = t + it * 256;
        int node = i >> 5, ch = i & 31;
        int gn = base + node;
        float4 v = make_float4(0.f, 0.f, 0.f, 0.f);
        if (gn < N) {
            if (ch < 16) {
                v = *reinterpret_cast<const float4*>(g_agg + (long long)gn * 64 + ch * 4);
                float s = invd_sm[node];
                v.x *= s; v.y *= s; v.z *= s; v.w *= s;
            } else {
                v = *reinterpret_cast<const float4*>(u + (long long)gn * 64 + (ch - 16) * 4);
            }
        }
        uint32_t h01 = pack_bf2(v.x, v.y);
        uint32_t h23 = pack_bf2(v.z, v.w);
        uint32_t l01 = pack_bf2(v.x - bf_lo(h01), v.y - bf_hi(h01));
        uint32_t l23 = pack_bf2(v.z - bf_lo(h23), v.w - bf_hi(h23));
        uint32_t off = (uint32_t)(node * 136 + ch * 4) * 2;
        *reinterpret_cast<uint2*>(smem + SO_AHI + off) = make_uint2(h01, h23);
        *reinterpret_cast<uint2*>(smem + SO_ALO + off) = make_uint2(l01, l23);
    }

    // --- stage Wt[n][k] = (k<64 ? W[k][n] : Bm[k-64][n]), hi/lo ---
    #pragma unroll
    for (int it = 0; it < 32; it++) {
        int i = t + it * 256;
        int n = i & 63, k = i >> 6;
        float wv = (k < 64) ? W[k * 64 + n] : Bm[(k - 64) * 64 + n];
        __nv_bfloat16 whi = __float2bfloat16(wv);
        __nv_bfloat16 wlo = __float2bfloat16(wv - __bfloat162float(whi));
        uint32_t off = (uint32_t)(n * 136 + k) * 2;
        *reinterpret_cast<__nv_bfloat16*>(smem + SO_WHI + off) = whi;
        *reinterpret_cast<__nv_bfloat16*>(smem + SO_WLO + off) = wlo;
    }

    // --- stage WpT[p][k] = Wp[k][p], hi/lo, stride 72 ---
    #pragma unroll
    for (int it = 0; it < 8; it++) {
        int i = t + it * 256;
        int p = i & 31, k = i >> 5;
        float wv = Wp[k * 32 + p];
        __nv_bfloat16 whi = __float2bfloat16(wv);
        __nv_bfloat16 wlo = __float2bfloat16(wv - __bfloat162float(whi));
        uint32_t off = (uint32_t)(p * 72 + k) * 2;
        *reinterpret_cast<__nv_bfloat16*>(smem + SO_WPH + off) = whi;
        *reinterpret_cast<__nv_bfloat16*>(smem + SO_WPL + off) = wlo;
    }
    __syncthreads();

    // --- main GEMM: 1 m-tile x 8 n-tiles, 3 passes ---
    float acc[8][4];
    #pragma unroll
    for (int n = 0; n < 8; n++)
        #pragma unroll
        for (int q = 0; q < 4; q++) acc[n][q] = 0.f;

    // A frag addr: rows w*16 + (l&15), col-half (l>>4)*8
    const uint32_t a_off = (uint32_t)((w * 16 + (l & 15)) * 136 + (l >> 4) * 8) * 2;
    // B x4 frag addr: two n-tiles; row (l&7) + ((l>>4)&1)*8, col-half ((l>>3)&1)*8
    const uint32_t b_off = (uint32_t)(((l & 7) + ((l >> 4) & 1) * 8) * 136 +
                                      ((l >> 3) & 1) * 8) * 2;

    auto gemm_pass = [&](uint32_t abase, uint32_t bbase) {
        #pragma unroll
        for (int kt = 0; kt < 8; kt++) {
            uint32_t af[4];
            ldsm_x4(abase + a_off + kt * 32, af);
            #pragma unroll
            for (int np = 0; np < 4; np++) {          // pair of n-tiles
                uint32_t bq[4];
                ldsm_x4(bbase + b_off + np * (16 * 136 * 2) + kt * 32, bq);
                mma16816(acc[2 * np],     af, bq);       // {bq0,bq1}
                mma16816(acc[2 * np + 1], af, bq + 2);   // {bq2,bq3}
            }
        }
    };
    gemm_pass(sb + SO_AHI, sb + SO_WHI);
    gemm_pass(sb + SO_AHI, sb + SO_WLO);
    gemm_pass(sb + SO_ALO, sb + SO_WHI);

    // --- epilogue: bias+relu, store x_new, head A-frags from regs ---
    uint32_t xh[8][2], xl[8][2];
    {
        int r0 = base + w * 16 + (l >> 2);
        #pragma unroll
        for (int n = 0; n < 8; n++) {
            int c = n * 8 + (l & 3) * 2;
            float b0 = bs[c], b1 = bs[c + 1];
            float d0 = fmaxf(acc[n][0] + b0, 0.f);
            float d1 = fmaxf(acc[n][1] + b1, 0.f);
            float d2 = fmaxf(acc[n][2] + b0, 0.f);
            float d3 = fmaxf(acc[n][3] + b1, 0.f);
            uint32_t h01 = pack_bf2(d0, d1);
            uint32_t h23 = pack_bf2(d2, d3);
            xh[n][0] = h01;
            xh[n][1] = h23;
            xl[n][0] = pack_bf2(d0 - bf_lo(h01), d1 - bf_hi(h01));
            xl[n][1] = pack_bf2(d2 - bf_lo(h23), d3 - bf_hi(h23));
            if (r0 < N)
                *reinterpret_cast<float2*>(out + (long long)r0 * 64 + c) =
                    make_float2(d0, d1);
            if (r0 + 8 < N)
                *reinterpret_cast<float2*>(out + (long long)(r0 + 8) * 64 + c) =
                    make_float2(d2, d3);
        }
    }

    // --- head GEMM: y = x_new @ Wp (+bp), 3 passes, A-frags from regs ---
    float y[4][4];
    #pragma unroll
    for (int nt = 0; nt < 4; nt++)
        #pragma unroll
        for (int q = 0; q < 4; q++) y[nt][q] = 0.f;

    const uint32_t p_off = (uint32_t)(((l & 7) + ((l >> 4) & 1) * 8) * 72 +
                                      ((l >> 3) & 1) * 8) * 2;

    auto head_pass = [&](uint32_t (*xf)[2], uint32_t pbase) {
        #pragma unroll
        for (int kk = 0; kk < 4; kk++) {
            uint32_t afr[4] = { xf[2 * kk][0], xf[2 * kk][1],
                                xf[2 * kk + 1][0], xf[2 * kk + 1][1] };
            #pragma unroll
            for (int np = 0; np < 2; np++) {
                uint32_t bq[4];
                ldsm_x4(pbase + p_off + np * (16 * 72 * 2) + kk * 32, bq);
                mma16816(y[2 * np],     afr, bq);
                mma16816(y[2 * np + 1], afr, bq + 2);
            }
        }
    };
    head_pass(xh, sb + SO_WPH);
    head_pass(xh, sb + SO_WPL);
    head_pass(xl, sb + SO_WPH);

    // --- store y ---
    {
        float* outy = out + (long long)N * 64;
        int r0 = base + w * 16 + (l >> 2);
        #pragma unroll
        for (int nt = 0; nt < 4; nt++) {
            int c = nt * 8 + (l & 3) * 2;
            float q0 = y[nt][0] + bps[c];
            float q1 = y[nt][1] + bps[c + 1];
            float q2 = y[nt][2] + bps[c];
            float q3 = y[nt][3] + bps[c + 1];
            if (r0 < N)
                *reinterpret_cast<float2*>(outy + (long long)r0 * 32 + c) =
                    make_float2(q0, q1);
            if (r0 + 8 < N)
                *reinterpret_cast<float2*>(outy + (long long)(r0 + 8) * 32 + c) =
                    make_float2(q2, q3);
        }
    }
}

// ---------------------------------------------------------------------------
extern "C" void kernel_launch(void* const* d_in, const int* in_sizes, int n_in,
                              void* d_out, int out_size)
{
    const float* x  = (const float*)d_in[0];
    const float* u  = (const float*)d_in[1];
    const void*  ei = d_in[2];
    const float* W  = (const float*)d_in[3];
    const float* B  = (const float*)d_in[4];
    const float* b  = (const float*)d_in[5];
    const float* Wp = (const float*)d_in[6];
    const float* bp = (const float*)d_in[7];
    float* out = (float*)d_out;

    int N = in_sizes[0] / 64;
    int E = in_sizes[2] / 2;

    cudaFuncSetAttribute(update_kernel,
                         cudaFuncAttributeMaxDynamicSharedMemorySize, SMEM_BYTES);

    detect_idx_kernel<<<1, 32>>>(ei, E, N);

    long long nagg4 = ((long long)N * 64) / 4;
    int init_blocks = (int)((nagg4 + 255) / 256);
    init_kernel<<<init_blocks, 256>>>(nagg4, N);

    long long sc_threads = (long long)E * 16;
    int sc_blocks = (int)((sc_threads + 255) / 256);
    scatter_kernel<<<sc_blocks, 256>>>(x, ei, E);

    int up_blocks = (N + 127) / 128;
    update_kernel<<<up_blocks, 256, SMEM_BYTES>>>(u, W, B, b, Wp, bp, out, N);
}

// round 9
// speedup vs baseline: 1.3146x; 1.0356x over previous
#include <cuda_runtime.h>
#include <cuda_bf16.h>
#include <cstdint>

// ---------------------------------------------------------------------------
// RecurrentGraphNeuralNet v8: HMMA bf16 split-precision update (3 passes),
// weight image precomputed once + cp.async'd per block, single sync.
// ---------------------------------------------------------------------------

#define MAXN 100000

__device__ float g_agg[(long long)MAXN * 64];
__device__ float g_deg[MAXN];
__device__ int   g_is64;

// Weight image: [Whi 17408][Wlo 17408][Wph 4608][Wpl 4608][bs 256][bps 128]
#define IMG_WHI 0
#define IMG_WLO 17408
#define IMG_WPH 34816
#define IMG_WPL 39424
#define IMG_BS  44032
#define IMG_BPS 44288
#define IMG_BYTES 44416
__device__ __align__(128) unsigned char g_wimg[IMG_BYTES];

// ---------------------------------------------------------------------------
__device__ __forceinline__ uint32_t smem_u32(const void* p) {
    uint32_t a;
    asm("{ .reg .u64 t; cvta.to.shared.u64 t, %1; cvt.u32.u64 %0, t; }"
        : "=r"(a) : "l"(p));
    return a;
}
__device__ __forceinline__ void ldsm_x4(uint32_t addr, uint32_t r[4]) {
    asm volatile("ldmatrix.sync.aligned.m8n8.x4.shared.b16 {%0,%1,%2,%3}, [%4];"
        : "=r"(r[0]), "=r"(r[1]), "=r"(r[2]), "=r"(r[3]) : "r"(addr));
}
__device__ __forceinline__ void mma16816(float d[4], const uint32_t a[4],
                                         const uint32_t b[2]) {
    asm volatile(
        "mma.sync.aligned.m16n8k16.row.col.f32.bf16.bf16.f32 "
        "{%0,%1,%2,%3}, {%4,%5,%6,%7}, {%8,%9}, {%0,%1,%2,%3};"
        : "+f"(d[0]), "+f"(d[1]), "+f"(d[2]), "+f"(d[3])
        : "r"(a[0]), "r"(a[1]), "r"(a[2]), "r"(a[3]), "r"(b[0]), "r"(b[1]));
}
__device__ __forceinline__ void cp_async16(uint32_t dst, const void* src) {
    asm volatile("cp.async.cg.shared.global [%0], [%1], 16;"
                 :: "r"(dst), "l"(src) : "memory");
}
__device__ __forceinline__ uint32_t pack_bf2(float lo, float hi) {
    __nv_bfloat162 h = __floats2bfloat162_rn(lo, hi);
    return *reinterpret_cast<uint32_t*>(&h);
}
__device__ __forceinline__ float bf_lo(uint32_t w) {
    __nv_bfloat16 h = *reinterpret_cast<__nv_bfloat16*>(&w);
    return __bfloat162float(h);
}
__device__ __forceinline__ float bf_hi(uint32_t w) {
    uint32_t s = w >> 16;
    __nv_bfloat16 h = *reinterpret_cast<__nv_bfloat16*>(&s);
    return __bfloat162float(h);
}

// SMEM layout (bytes); weight segments mirror the global image contiguously.
#define SO_AHI   0            // 128 x 136 bf16
#define SO_ALO   34816
#define SO_WIMG  69632        // image copied here: WHI..BPS
#define SO_WHI   (SO_WIMG + IMG_WHI)
#define SO_WLO   (SO_WIMG + IMG_WLO)
#define SO_WPH   (SO_WIMG + IMG_WPH)
#define SO_WPL   (SO_WIMG + IMG_WPL)
#define SO_BS    (SO_WIMG + IMG_BS)
#define SO_BPS   (SO_WIMG + IMG_BPS)
#define SMEM_BYTES (SO_WIMG + IMG_BYTES)   // 114048

// ---------------------------------------------------------------------------
__global__ void detect_idx_kernel(const void* ei, int E, int N) {
    if (blockIdx.x == 0 && threadIdx.x == 0) {
        const long long* p = (const long long*)ei;
        int is64 = 1;
        #pragma unroll
        for (int i = 0; i < 8; i++) {
            long long v = p[i];
            if (v < 0 || v >= (long long)N) { is64 = 0; break; }
        }
        g_is64 = is64;
    }
}

__global__ void init_kernel(long long nagg4, int n) {
    long long i = (long long)blockIdx.x * blockDim.x + threadIdx.x;
    if (i < nagg4)
        *reinterpret_cast<float4*>(g_agg + i * 4) = make_float4(0.f, 0.f, 0.f, 0.f);
    if (i < n) g_deg[i] = 0.f;
}

// Build the hi/lo-split, transposed, ldmatrix-ready weight image (once).
__global__ void setup_weights_kernel(
    const float* __restrict__ W, const float* __restrict__ Bm,
    const float* __restrict__ Wp, const float* __restrict__ b,
    const float* __restrict__ bp)
{
    int i = blockIdx.x * blockDim.x + threadIdx.x;
    if (i < 8192) {                      // Wt[n][k] hi/lo, stride 136
        int n = i & 63, k = i >> 6;
        float wv = (k < 64) ? W[k * 64 + n] : Bm[(k - 64) * 64 + n];
        __nv_bfloat16 whi = __float2bfloat16(wv);
        __nv_bfloat16 wlo = __float2bfloat16(wv - __bfloat162float(whi));
        uint32_t off = (uint32_t)(n * 136 + k) * 2;
        *reinterpret_cast<__nv_bfloat16*>(g_wimg + IMG_WHI + off) = whi;
        *reinterpret_cast<__nv_bfloat16*>(g_wimg + IMG_WLO + off) = wlo;
    } else if (i < 10240) {              // WpT[p][k] hi/lo, stride 72
        int j = i - 8192;
        int p = j & 31, k = j >> 5;
        float wv = Wp[k * 32 + p];
        __nv_bfloat16 whi = __float2bfloat16(wv);
        __nv_bfloat16 wlo = __float2bfloat16(wv - __bfloat162float(whi));
        uint32_t off = (uint32_t)(p * 72 + k) * 2;
        *reinterpret_cast<__nv_bfloat16*>(g_wimg + IMG_WPH + off) = whi;
        *reinterpret_cast<__nv_bfloat16*>(g_wimg + IMG_WPL + off) = wlo;
    } else if (i < 10304) {              // bs
        int j = i - 10240;
        *reinterpret_cast<float*>(g_wimg + IMG_BS + j * 4) = b[j];
    } else if (i < 10336) {              // bps
        int j = i - 10304;
        *reinterpret_cast<float*>(g_wimg + IMG_BPS + j * 4) = bp[j];
    }
}

__global__ __launch_bounds__(256) void scatter_kernel(
    const float* __restrict__ x, const void* __restrict__ ei_raw, int E)
{
    long long idx = (long long)blockIdx.x * blockDim.x + threadIdx.x;
    long long total = (long long)E * 16;
    if (idx >= total) return;

    const int is64 = g_is64;
    int e  = (int)(idx >> 4);
    int f4 = ((int)idx & 15) * 4;

    int s, d;
    if (is64) {
        const long long* ei = (const long long*)ei_raw;
        s = (int)ei[e];
        d = (int)ei[(long long)E + e];
    } else {
        const int* ei = (const int*)ei_raw;
        s = ei[e];
        d = ei[E + e];
    }

    float4 v = *reinterpret_cast<const float4*>(x + (long long)s * 64 + f4);
    float* dst = g_agg + (long long)d * 64 + f4;
    asm volatile("red.global.add.v4.f32 [%0], {%1, %2, %3, %4};"
                 :: "l"(dst), "f"(v.x), "f"(v.y), "f"(v.z), "f"(v.w)
                 : "memory");

    if ((idx & 15) == 0) atomicAdd(&g_deg[d], 1.0f);
}

// ---------------------------------------------------------------------------
// 128 nodes/block, 256 threads (8 warps); warp w owns rows [w*16, w*16+16).
__global__ __launch_bounds__(256, 2) void update_kernel(
    const float* __restrict__ u, float* __restrict__ out, int N)
{
    extern __shared__ char smem[];
    const uint32_t sb = smem_u32(smem);
    const int t = threadIdx.x;
    const int l = t & 31;
    const int w = t >> 5;
    const int base = blockIdx.x * 128;

    float* bs  = (float*)(smem + SO_BS);
    float* bps = (float*)(smem + SO_BPS);

    // --- 1) async weight-image copy (L2-hit, 16B chunks) ---
    for (int i = t; i < IMG_BYTES / 16; i += 256)
        cp_async16(sb + SO_WIMG + i * 16, g_wimg + i * 16);
    asm volatile("cp.async.commit_group;" ::: "memory");

    // --- 2) stage A = [mean | u], hi/lo, stride 136 (overlaps cp.async) ---
    // lane ch<16: mean chunk ch ; ch>=16: u chunk ch-16. node warp-uniform.
    #pragma unroll
    for (int it = 0; it < 16; it++) {
        int node = w + it * 8;
        int gn = base + node;
        int ch = l;
        float4 v = make_float4(0.f, 0.f, 0.f, 0.f);
        if (gn < N) {
            if (ch < 16) {
                v = *reinterpret_cast<const float4*>(g_agg + (long long)gn * 64 + ch * 4);
                float inv = 1.0f / fmaxf(g_deg[gn], 1.0f);
                v.x *= inv; v.y *= inv; v.z *= inv; v.w *= inv;
            } else {
                v = *reinterpret_cast<const float4*>(u + (long long)gn * 64 + (ch - 16) * 4);
            }
        }
        uint32_t h01 = pack_bf2(v.x, v.y);
        uint32_t h23 = pack_bf2(v.z, v.w);
        uint32_t l01 = pack_bf2(v.x - bf_lo(h01), v.y - bf_hi(h01));
        uint32_t l23 = pack_bf2(v.z - bf_lo(h23), v.w - bf_hi(h23));
        uint32_t off = (uint32_t)(node * 136 + ch * 4) * 2;
        *reinterpret_cast<uint2*>(smem + SO_AHI + off) = make_uint2(h01, h23);
        *reinterpret_cast<uint2*>(smem + SO_ALO + off) = make_uint2(l01, l23);
    }

    asm volatile("cp.async.wait_group 0;" ::: "memory");
    __syncthreads();          // the ONLY block-wide sync

    // --- 3) main GEMM: 1 m-tile x 8 n-tiles, 3 passes (hh, hl, lh) ---
    float acc[8][4];
    #pragma unroll
    for (int n = 0; n < 8; n++)
        #pragma unroll
        for (int q = 0; q < 4; q++) acc[n][q] = 0.f;

    const uint32_t a_off = (uint32_t)((w * 16 + (l & 15)) * 136 + (l >> 4) * 8) * 2;
    const uint32_t b_off = (uint32_t)(((l & 7) + ((l >> 4) & 1) * 8) * 136 +
                                      ((l >> 3) & 1) * 8) * 2;

    auto gemm_pass = [&](uint32_t abase, uint32_t bbase) {
        #pragma unroll
        for (int kt = 0; kt < 8; kt++) {
            uint32_t af[4];
            ldsm_x4(abase + a_off + kt * 32, af);
            #pragma unroll
            for (int np = 0; np < 4; np++) {
                uint32_t bq[4];
                ldsm_x4(bbase + b_off + np * (16 * 136 * 2) + kt * 32, bq);
                mma16816(acc[2 * np],     af, bq);
                mma16816(acc[2 * np + 1], af, bq + 2);
            }
        }
    };
    gemm_pass(sb + SO_AHI, sb + SO_WHI);
    gemm_pass(sb + SO_AHI, sb + SO_WLO);
    gemm_pass(sb + SO_ALO, sb + SO_WHI);

    // --- 4) epilogue: bias+relu, store x_new, head A-frags from regs ---
    uint32_t xh[8][2], xl[8][2];
    {
        int r0 = base + w * 16 + (l >> 2);
        #pragma unroll
        for (int n = 0; n < 8; n++) {
            int c = n * 8 + (l & 3) * 2;
            float b0 = bs[c], b1 = bs[c + 1];
            float d0 = fmaxf(acc[n][0] + b0, 0.f);
            float d1 = fmaxf(acc[n][1] + b1, 0.f);
            float d2 = fmaxf(acc[n][2] + b0, 0.f);
            float d3 = fmaxf(acc[n][3] + b1, 0.f);
            uint32_t h01 = pack_bf2(d0, d1);
            uint32_t h23 = pack_bf2(d2, d3);
            xh[n][0] = h01;
            xh[n][1] = h23;
            xl[n][0] = pack_bf2(d0 - bf_lo(h01), d1 - bf_hi(h01));
            xl[n][1] = pack_bf2(d2 - bf_lo(h23), d3 - bf_hi(h23));
            if (r0 < N)
                *reinterpret_cast<float2*>(out + (long long)r0 * 64 + c) =
                    make_float2(d0, d1);
            if (r0 + 8 < N)
                *reinterpret_cast<float2*>(out + (long long)(r0 + 8) * 64 + c) =
                    make_float2(d2, d3);
        }
    }

    // --- 5) head GEMM: y = x_new @ Wp (+bp), 3 passes ---
    float y[4][4];
    #pragma unroll
    for (int nt = 0; nt < 4; nt++)
        #pragma unroll
        for (int q = 0; q < 4; q++) y[nt][q] = 0.f;

    const uint32_t p_off = (uint32_t)(((l & 7) + ((l >> 4) & 1) * 8) * 72 +
                                      ((l >> 3) & 1) * 8) * 2;

    auto head_pass = [&](uint32_t (*xf)[2], uint32_t pbase) {
        #pragma unroll
        for (int kk = 0; kk < 4; kk++) {
            uint32_t afr[4] = { xf[2 * kk][0], xf[2 * kk][1],
                                xf[2 * kk + 1][0], xf[2 * kk + 1][1] };
            #pragma unroll
            for (int np = 0; np < 2; np++) {
                uint32_t bq[4];
                ldsm_x4(pbase + p_off + np * (16 * 72 * 2) + kk * 32, bq);
                mma16816(y[2 * np],     afr, bq);
                mma16816(y[2 * np + 1], afr, bq + 2);
            }
        }
    };
    head_pass(xh, sb + SO_WPH);
    head_pass(xh, sb + SO_WPL);
    head_pass(xl, sb + SO_WPH);

    // --- 6) store y ---
    {
        float* outy = out + (long long)N * 64;
        int r0 = base + w * 16 + (l >> 2);
        #pragma unroll
        for (int nt = 0; nt < 4; nt++) {
            int c = nt * 8 + (l & 3) * 2;
            float q0 = y[nt][0] + bps[c];
            float q1 = y[nt][1] + bps[c + 1];
            float q2 = y[nt][2] + bps[c];
            float q3 = y[nt][3] + bps[c + 1];
            if (r0 < N)
                *reinterpret_cast<float2*>(outy + (long long)r0 * 32 + c) =
                    make_float2(q0, q1);
            if (r0 + 8 < N)
                *reinterpret_cast<float2*>(outy + (long long)(r0 + 8) * 32 + c) =
                    make_float2(q2, q3);
        }
    }
}

// ---------------------------------------------------------------------------
extern "C" void kernel_launch(void* const* d_in, const int* in_sizes, int n_in,
                              void* d_out, int out_size)
{
    const float* x  = (const float*)d_in[0];
    const float* u  = (const float*)d_in[1];
    const void*  ei = d_in[2];
    const float* W  = (const float*)d_in[3];
    const float* B  = (const float*)d_in[4];
    const float* b  = (const float*)d_in[5];
    const float* Wp = (const float*)d_in[6];
    const float* bp = (const float*)d_in[7];
    float* out = (float*)d_out;

    int N = in_sizes[0] / 64;
    int E = in_sizes[2] / 2;

    cudaFuncSetAttribute(update_kernel,
                         cudaFuncAttributeMaxDynamicSharedMemorySize, SMEM_BYTES);

    detect_idx_kernel<<<1, 32>>>(ei, E, N);

    long long nagg4 = ((long long)N * 64) / 4;
    int init_blocks = (int)((nagg4 + 255) / 256);
    init_kernel<<<init_blocks, 256>>>(nagg4, N);

    setup_weights_kernel<<<41, 256>>>(W, B, Wp, b, bp);

    long long sc_threads = (long long)E * 16;
    int sc_blocks = (int)((sc_threads + 255) / 256);
    scatter_kernel<<<sc_blocks, 256>>>(x, ei, E);

    int up_blocks = (N + 127) / 128;
    update_kernel<<<up_blocks, 256, SMEM_BYTES>>>(u, out, N);
}

// round 10
// speedup vs baseline: 1.3782x; 1.0484x over previous
#include <cuda_runtime.h>
#include <cuda_bf16.h>
#include <cstdint>

// ---------------------------------------------------------------------------
// RecurrentGraphNeuralNet v9: scatter with 4 edges/thread (MLP=4 batched
// index->gather->RED phases). Update kernel: HMMA bf16 split-precision
// (3 passes), cp.async'd precomputed weight image, single sync (v8).
// ---------------------------------------------------------------------------

#define MAXN 100000

__device__ float g_agg[(long long)MAXN * 64];
__device__ float g_deg[MAXN];
__device__ int   g_is64;

// Weight image: [Whi 17408][Wlo 17408][Wph 4608][Wpl 4608][bs 256][bps 128]
#define IMG_WHI 0
#define IMG_WLO 17408
#define IMG_WPH 34816
#define IMG_WPL 39424
#define IMG_BS  44032
#define IMG_BPS 44288
#define IMG_BYTES 44416
__device__ __align__(128) unsigned char g_wimg[IMG_BYTES];

// ---------------------------------------------------------------------------
__device__ __forceinline__ uint32_t smem_u32(const void* p) {
    uint32_t a;
    asm("{ .reg .u64 t; cvta.to.shared.u64 t, %1; cvt.u32.u64 %0, t; }"
        : "=r"(a) : "l"(p));
    return a;
}
__device__ __forceinline__ void ldsm_x4(uint32_t addr, uint32_t r[4]) {
    asm volatile("ldmatrix.sync.aligned.m8n8.x4.shared.b16 {%0,%1,%2,%3}, [%4];"
        : "=r"(r[0]), "=r"(r[1]), "=r"(r[2]), "=r"(r[3]) : "r"(addr));
}
__device__ __forceinline__ void mma16816(float d[4], const uint32_t a[4],
                                         const uint32_t b[2]) {
    asm volatile(
        "mma.sync.aligned.m16n8k16.row.col.f32.bf16.bf16.f32 "
        "{%0,%1,%2,%3}, {%4,%5,%6,%7}, {%8,%9}, {%0,%1,%2,%3};"
        : "+f"(d[0]), "+f"(d[1]), "+f"(d[2]), "+f"(d[3])
        : "r"(a[0]), "r"(a[1]), "r"(a[2]), "r"(a[3]), "r"(b[0]), "r"(b[1]));
}
__device__ __forceinline__ void cp_async16(uint32_t dst, const void* src) {
    asm volatile("cp.async.cg.shared.global [%0], [%1], 16;"
                 :: "r"(dst), "l"(src) : "memory");
}
__device__ __forceinline__ uint32_t pack_bf2(float lo, float hi) {
    __nv_bfloat162 h = __floats2bfloat162_rn(lo, hi);
    return *reinterpret_cast<uint32_t*>(&h);
}
__device__ __forceinline__ float bf_lo(uint32_t w) {
    __nv_bfloat16 h = *reinterpret_cast<__nv_bfloat16*>(&w);
    return __bfloat162float(h);
}
__device__ __forceinline__ float bf_hi(uint32_t w) {
    uint32_t s = w >> 16;
    __nv_bfloat16 h = *reinterpret_cast<__nv_bfloat16*>(&s);
    return __bfloat162float(h);
}

// SMEM layout (bytes)
#define SO_AHI   0
#define SO_ALO   34816
#define SO_WIMG  69632
#define SO_WHI   (SO_WIMG + IMG_WHI)
#define SO_WLO   (SO_WIMG + IMG_WLO)
#define SO_WPH   (SO_WIMG + IMG_WPH)
#define SO_WPL   (SO_WIMG + IMG_WPL)
#define SO_BS    (SO_WIMG + IMG_BS)
#define SO_BPS   (SO_WIMG + IMG_BPS)
#define SMEM_BYTES (SO_WIMG + IMG_BYTES)   // 114048

// ---------------------------------------------------------------------------
__global__ void detect_idx_kernel(const void* ei, int E, int N) {
    if (blockIdx.x == 0 && threadIdx.x == 0) {
        const long long* p = (const long long*)ei;
        int is64 = 1;
        #pragma unroll
        for (int i = 0; i < 8; i++) {
            long long v = p[i];
            if (v < 0 || v >= (long long)N) { is64 = 0; break; }
        }
        g_is64 = is64;
    }
}

__global__ void init_kernel(long long nagg4, int n) {
    long long i = (long long)blockIdx.x * blockDim.x + threadIdx.x;
    if (i < nagg4)
        *reinterpret_cast<float4*>(g_agg + i * 4) = make_float4(0.f, 0.f, 0.f, 0.f);
    if (i < n) g_deg[i] = 0.f;
}

// Build the hi/lo-split, transposed, ldmatrix-ready weight image (once).
__global__ void setup_weights_kernel(
    const float* __restrict__ W, const float* __restrict__ Bm,
    const float* __restrict__ Wp, const float* __restrict__ b,
    const float* __restrict__ bp)
{
    int i = blockIdx.x * blockDim.x + threadIdx.x;
    if (i < 8192) {
        int n = i & 63, k = i >> 6;
        float wv = (k < 64) ? W[k * 64 + n] : Bm[(k - 64) * 64 + n];
        __nv_bfloat16 whi = __float2bfloat16(wv);
        __nv_bfloat16 wlo = __float2bfloat16(wv - __bfloat162float(whi));
        uint32_t off = (uint32_t)(n * 136 + k) * 2;
        *reinterpret_cast<__nv_bfloat16*>(g_wimg + IMG_WHI + off) = whi;
        *reinterpret_cast<__nv_bfloat16*>(g_wimg + IMG_WLO + off) = wlo;
    } else if (i < 10240) {
        int j = i - 8192;
        int p = j & 31, k = j >> 5;
        float wv = Wp[k * 32 + p];
        __nv_bfloat16 whi = __float2bfloat16(wv);
        __nv_bfloat16 wlo = __float2bfloat16(wv - __bfloat162float(whi));
        uint32_t off = (uint32_t)(p * 72 + k) * 2;
        *reinterpret_cast<__nv_bfloat16*>(g_wimg + IMG_WPH + off) = whi;
        *reinterpret_cast<__nv_bfloat16*>(g_wimg + IMG_WPL + off) = wlo;
    } else if (i < 10304) {
        int j = i - 10240;
        *reinterpret_cast<float*>(g_wimg + IMG_BS + j * 4) = b[j];
    } else if (i < 10336) {
        int j = i - 10304;
        *reinterpret_cast<float*>(g_wimg + IMG_BPS + j * 4) = bp[j];
    }
}

// ---------------------------------------------------------------------------
// Scatter v2: 4 edges/thread (segments of Q edges), batched phases -> MLP=4.
__global__ __launch_bounds__(256) void scatter_kernel(
    const float* __restrict__ x, const void* __restrict__ ei_raw, int E, int Q)
{
    long long idx = (long long)blockIdx.x * blockDim.x + threadIdx.x;
    long long total = (long long)Q * 16;
    if (idx >= total) return;

    const int is64 = g_is64;
    const int e0 = (int)(idx >> 4);
    const int f4 = ((int)idx & 15) * 4;

    // phase 1: indices for all 4 edges
    int s[4], d[4];
    bool ok[4];
    #pragma unroll
    for (int j = 0; j < 4; j++) {
        int e = e0 + j * Q;
        ok[j] = (e < E);
        s[j] = 0; d[j] = 0;
        if (ok[j]) {
            if (is64) {
                const long long* ei = (const long long*)ei_raw;
                s[j] = (int)__ldg(ei + e);
                d[j] = (int)__ldg(ei + (long long)E + e);
            } else {
                const int* ei = (const int*)ei_raw;
                s[j] = __ldg(ei + e);
                d[j] = __ldg(ei + E + e);
            }
        }
    }

    // phase 2: gathers (independent -> 4 loads in flight)
    float4 v[4];
    #pragma unroll
    for (int j = 0; j < 4; j++) {
        v[j] = make_float4(0.f, 0.f, 0.f, 0.f);
        if (ok[j])
            v[j] = *reinterpret_cast<const float4*>(x + (long long)s[j] * 64 + f4);
    }

    // phase 3: reductions
    #pragma unroll
    for (int j = 0; j < 4; j++) {
        if (ok[j]) {
            float* dst = g_agg + (long long)d[j] * 64 + f4;
            asm volatile("red.global.add.v4.f32 [%0], {%1, %2, %3, %4};"
                         :: "l"(dst), "f"(v[j].x), "f"(v[j].y), "f"(v[j].z), "f"(v[j].w)
                         : "memory");
        }
    }

    if (f4 == 0) {
        #pragma unroll
        for (int j = 0; j < 4; j++)
            if (ok[j]) atomicAdd(&g_deg[d[j]], 1.0f);
    }
}

// ---------------------------------------------------------------------------
// Update v8 (unchanged): 128 nodes/block, 256 threads, HMMA 3-pass.
__global__ __launch_bounds__(256, 2) void update_kernel(
    const float* __restrict__ u, float* __restrict__ out, int N)
{
    extern __shared__ char smem[];
    const uint32_t sb = smem_u32(smem);
    const int t = threadIdx.x;
    const int l = t & 31;
    const int w = t >> 5;
    const int base = blockIdx.x * 128;

    float* bs  = (float*)(smem + SO_BS);
    float* bps = (float*)(smem + SO_BPS);

    for (int i = t; i < IMG_BYTES / 16; i += 256)
        cp_async16(sb + SO_WIMG + i * 16, g_wimg + i * 16);
    asm volatile("cp.async.commit_group;" ::: "memory");

    #pragma unroll
    for (int it = 0; it < 16; it++) {
        int node = w + it * 8;
        int gn = base + node;
        int ch = l;
        float4 v = make_float4(0.f, 0.f, 0.f, 0.f);
        if (gn < N) {
            if (ch < 16) {
                v = *reinterpret_cast<const float4*>(g_agg + (long long)gn * 64 + ch * 4);
                float inv = 1.0f / fmaxf(g_deg[gn], 1.0f);
                v.x *= inv; v.y *= inv; v.z *= inv; v.w *= inv;
            } else {
                v = *reinterpret_cast<const float4*>(u + (long long)gn * 64 + (ch - 16) * 4);
            }
        }
        uint32_t h01 = pack_bf2(v.x, v.y);
        uint32_t h23 = pack_bf2(v.z, v.w);
        uint32_t l01 = pack_bf2(v.x - bf_lo(h01), v.y - bf_hi(h01));
        uint32_t l23 = pack_bf2(v.z - bf_lo(h23), v.w - bf_hi(h23));
        uint32_t off = (uint32_t)(node * 136 + ch * 4) * 2;
        *reinterpret_cast<uint2*>(smem + SO_AHI + off) = make_uint2(h01, h23);
        *reinterpret_cast<uint2*>(smem + SO_ALO + off) = make_uint2(l01, l23);
    }

    asm volatile("cp.async.wait_group 0;" ::: "memory");
    __syncthreads();

    float acc[8][4];
    #pragma unroll
    for (int n = 0; n < 8; n++)
        #pragma unroll
        for (int q = 0; q < 4; q++) acc[n][q] = 0.f;

    const uint32_t a_off = (uint32_t)((w * 16 + (l & 15)) * 136 + (l >> 4) * 8) * 2;
    const uint32_t b_off = (uint32_t)(((l & 7) + ((l >> 4) & 1) * 8) * 136 +
                                      ((l >> 3) & 1) * 8) * 2;

    auto gemm_pass = [&](uint32_t abase, uint32_t bbase) {
        #pragma unroll
        for (int kt = 0; kt < 8; kt++) {
            uint32_t af[4];
            ldsm_x4(abase + a_off + kt * 32, af);
            #pragma unroll
            for (int np = 0; np < 4; np++) {
                uint32_t bq[4];
                ldsm_x4(bbase + b_off + np * (16 * 136 * 2) + kt * 32, bq);
                mma16816(acc[2 * np],     af, bq);
                mma16816(acc[2 * np + 1], af, bq + 2);
            }
        }
    };
    gemm_pass(sb + SO_AHI, sb + SO_WHI);
    gemm_pass(sb + SO_AHI, sb + SO_WLO);
    gemm_pass(sb + SO_ALO, sb + SO_WHI);

    uint32_t xh[8][2], xl[8][2];
    {
        int r0 = base + w * 16 + (l >> 2);
        #pragma unroll
        for (int n = 0; n < 8; n++) {
            int c = n * 8 + (l & 3) * 2;
            float b0 = bs[c], b1 = bs[c + 1];
            float d0 = fmaxf(acc[n][0] + b0, 0.f);
            float d1 = fmaxf(acc[n][1] + b1, 0.f);
            float d2 = fmaxf(acc[n][2] + b0, 0.f);
            float d3 = fmaxf(acc[n][3] + b1, 0.f);
            uint32_t h01 = pack_bf2(d0, d1);
            uint32_t h23 = pack_bf2(d2, d3);
            xh[n][0] = h01;
            xh[n][1] = h23;
            xl[n][0] = pack_bf2(d0 - bf_lo(h01), d1 - bf_hi(h01));
            xl[n][1] = pack_bf2(d2 - bf_lo(h23), d3 - bf_hi(h23));
            if (r0 < N)
                *reinterpret_cast<float2*>(out + (long long)r0 * 64 + c) =
                    make_float2(d0, d1);
            if (r0 + 8 < N)
                *reinterpret_cast<float2*>(out + (long long)(r0 + 8) * 64 + c) =
                    make_float2(d2, d3);
        }
    }

    float y[4][4];
    #pragma unroll
    for (int nt = 0; nt < 4; nt++)
        #pragma unroll
        for (int q = 0; q < 4; q++) y[nt][q] = 0.f;

    const uint32_t p_off = (uint32_t)(((l & 7) + ((l >> 4) & 1) * 8) * 72 +
                                      ((l >> 3) & 1) * 8) * 2;

    auto head_pass = [&](uint32_t (*xf)[2], uint32_t pbase) {
        #pragma unroll
        for (int kk = 0; kk < 4; kk++) {
            uint32_t afr[4] = { xf[2 * kk][0], xf[2 * kk][1],
                                xf[2 * kk + 1][0], xf[2 * kk + 1][1] };
            #pragma unroll
            for (int np = 0; np < 2; np++) {
                uint32_t bq[4];
                ldsm_x4(pbase + p_off + np * (16 * 72 * 2) + kk * 32, bq);
                mma16816(y[2 * np],     afr, bq);
                mma16816(y[2 * np + 1], afr, bq + 2);
            }
        }
    };
    head_pass(xh, sb + SO_WPH);
    head_pass(xh, sb + SO_WPL);
    head_pass(xl, sb + SO_WPH);

    {
        float* outy = out + (long long)N * 64;
        int r0 = base + w * 16 + (l >> 2);
        #pragma unroll
        for (int nt = 0; nt < 4; nt++) {
            int c = nt * 8 + (l & 3) * 2;
            float q0 = y[nt][0] + bps[c];
            float q1 = y[nt][1] + bps[c + 1];
            float q2 = y[nt][2] + bps[c];
            float q3 = y[nt][3] + bps[c + 1];
            if (r0 < N)
                *reinterpret_cast<float2*>(outy + (long long)r0 * 32 + c) =
                    make_float2(q0, q1);
            if (r0 + 8 < N)
                *reinterpret_cast<float2*>(outy + (long long)(r0 + 8) * 32 + c) =
                    make_float2(q2, q3);
        }
    }
}

// ---------------------------------------------------------------------------
extern "C" void kernel_launch(void* const* d_in, const int* in_sizes, int n_in,
                              void* d_out, int out_size)
{
    const float* x  = (const float*)d_in[0];
    const float* u  = (const float*)d_in[1];
    const void*  ei = d_in[2];
    const float* W  = (const float*)d_in[3];
    const float* B  = (const float*)d_in[4];
    const float* b  = (const float*)d_in[5];
    const float* Wp = (const float*)d_in[6];
    const float* bp = (const float*)d_in[7];
    float* out = (float*)d_out;

    int N = in_sizes[0] / 64;
    int E = in_sizes[2] / 2;

    cudaFuncSetAttribute(update_kernel,
                         cudaFuncAttributeMaxDynamicSharedMemorySize, SMEM_BYTES);

    detect_idx_kernel<<<1, 32>>>(ei, E, N);

    long long nagg4 = ((long long)N * 64) / 4;
    int init_blocks = (int)((nagg4 + 255) / 256);
    init_kernel<<<init_blocks, 256>>>(nagg4, N);

    setup_weights_kernel<<<41, 256>>>(W, B, Wp, b, bp);

    int Q = (E + 3) / 4;                       // edges per segment
    long long sc_threads = (long long)Q * 16;
    int sc_blocks = (int)((sc_threads + 255) / 256);
    scatter_kernel<<<sc_blocks, 256>>>(x, ei, E, Q);

    int up_blocks = (N + 127) / 128;
    update_kernel<<<up_blocks, 256, SMEM_BYTES>>>(u, out, N);
}